// round 1
// baseline (speedup 1.0000x reference)
#include <cuda_runtime.h>
#include <cstdint>
#include <math.h>

// ---------------------------------------------------------------------------
// Bidirectional 3-layer ConvLSTM encoder.
// B=8, T=24. L1: 48x56, Cin=6,  F=32. L2: 24x28, Cin=64, F=32. L3: 12x14, Cin=64, F=12.
// ---------------------------------------------------------------------------

#define BB 8
#define TT 24

// ---- scratch (__device__ globals: the allowed no-alloc workaround) ----
__device__ float g_seq1[(size_t)BB * TT * 48 * 56 * 64];   // 132 MB
__device__ float g_p1  [(size_t)BB * TT * 24 * 28 * 64];
__device__ float g_seq2[(size_t)BB * TT * 24 * 28 * 64];
__device__ float g_p2  [(size_t)BB * TT * 12 * 14 * 64];
__device__ float g_z   [(size_t)2 * BB * 48 * 56 * 128];   // z scratch, max layer-1 size
__device__ float g_h   [(size_t)2 * BB * 48 * 56 * 32];    // h state (max size), reused per layer
__device__ float g_c   [(size_t)2 * BB * 48 * 56 * 32];    // c state
__device__ float g_w1f[9 * 38 * 128], g_w1b[9 * 38 * 128];
__device__ float g_w2f[9 * 96 * 128], g_w2b[9 * 96 * 128];
__device__ float g_w3f[9 * 76 * 48],  g_w3b[9 * 76 * 48];

// ---------------------------------------------------------------------------
// Weight concat: wcat[k][ic][oc], ic in [0,CIN) from Wx, [CIN,CIN+F) from Wh.
// ---------------------------------------------------------------------------
__global__ void concat_w_kernel(const float* __restrict__ wx,
                                const float* __restrict__ wh,
                                float* __restrict__ wcat, int CIN, int F) {
    int OC = 4 * F, CH = CIN + F;
    int total = 9 * CH * OC;
    for (int i = blockIdx.x * blockDim.x + threadIdx.x; i < total;
         i += gridDim.x * blockDim.x) {
        int oc = i % OC;
        int r = i / OC;
        int ic = r % CH;
        int k = r / CH;
        wcat[i] = (ic < CIN) ? wx[((size_t)k * CIN + ic) * OC + oc]
                             : wh[((size_t)k * F + (ic - CIN)) * OC + oc];
    }
}

// ---------------------------------------------------------------------------
// One recurrent step, fused x-conv + h-conv, both directions.
// grid = (tilesH*tilesW, B, 2), block = 4F threads (1 thread = 1 gate channel).
// z[dir][b][y][x][oc] = bias[oc] + sum_{k,ic} in[k,ic] * wcat[k][ic][oc]
// ---------------------------------------------------------------------------
template <int CIN, int F, int H, int W>
__global__ __launch_bounds__(4 * F) void conv_step_kernel(
    const float* __restrict__ xin,     // [B,T,H,W,CIN]
    const float* __restrict__ hstate,  // [2,B,H,W,F]
    const float* __restrict__ wf, const float* __restrict__ wb,
    const float* __restrict__ bf, const float* __restrict__ bb,
    float* __restrict__ zbuf,          // [2,B,H,W,4F]
    int j) {
    constexpr int OC = 4 * F;
    constexpr int CH = CIN + F;
    constexpr int TH = 4, TW = 14;
    constexpr int TW2 = TW + 2;                  // 16
    constexpr int CSTRIDE = ((TH + 2) * TW2) | 1;  // 97, odd -> conflict-free loads
    constexpr int TILES_W = W / TW;

    __shared__ float s[CH * CSTRIDE];

    const int dir = blockIdx.z;
    const int b = blockIdx.y;
    const int tile = blockIdx.x;
    const int ty0 = (tile / TILES_W) * TH;
    const int tx0 = (tile % TILES_W) * TW;
    const int t = dir ? (TT - 1 - j) : j;

    const float* wc = dir ? wb : wf;
    const float* bi = dir ? bb : bf;
    const float* xb = xin + ((size_t)(b * TT + t)) * H * W * CIN;
    const float* hb = hstate + ((size_t)(dir * BB + b)) * H * W * F;

    const int tid = threadIdx.x;

    // Cooperative halo load, global [y][x][c] -> smem [c][y][x]
    constexpr int TOTAL = (TH + 2) * TW2 * CH;
    for (int idx = tid; idx < TOTAL; idx += OC) {
        int c = idx % CH;
        int p = idx / CH;
        int yy = p / TW2, xx = p % TW2;
        int gy = ty0 + yy - 1, gx = tx0 + xx - 1;
        float v = 0.f;
        if (gy >= 0 && gy < H && gx >= 0 && gx < W) {
            v = (c < CIN) ? xb[((size_t)gy * W + gx) * CIN + c]
                          : hb[((size_t)gy * W + gx) * F + (c - CIN)];
        }
        s[c * CSTRIDE + yy * TW2 + xx] = v;
    }
    __syncthreads();

    const int oc = tid;
    const float bv = bi[oc];
    float acc[TH][TW];
#pragma unroll
    for (int y = 0; y < TH; y++)
#pragma unroll
        for (int p = 0; p < TW; p++) acc[y][p] = bv;

    for (int c = 0; c < CH; c++) {
        const float* sc = s + c * CSTRIDE;
        float w[9];
#pragma unroll
        for (int k = 0; k < 9; k++) w[k] = wc[((size_t)k * CH + c) * OC + oc];
#pragma unroll
        for (int gy = 0; gy < TH + 2; gy++) {
            float seg[TW2];
#pragma unroll
            for (int k = 0; k < TW2; k++) seg[k] = sc[gy * TW2 + k];
#pragma unroll
            for (int dy = 0; dy < 3; dy++) {
                const int ry = gy - dy;
                if (ry >= 0 && ry < TH) {
#pragma unroll
                    for (int dx = 0; dx < 3; dx++) {
                        const float ww = w[dy * 3 + dx];
#pragma unroll
                        for (int p = 0; p < TW; p++)
                            acc[ry][p] = fmaf(ww, seg[p + dx], acc[ry][p]);
                    }
                }
            }
        }
    }

    float* zb = zbuf + ((size_t)(dir * BB + b) * H * W) * OC;
#pragma unroll
    for (int y = 0; y < TH; y++)
#pragma unroll
        for (int p = 0; p < TW; p++)
            zb[((size_t)(ty0 + y) * W + tx0 + p) * OC + oc] = acc[y][p];
}

// ---------------------------------------------------------------------------
// Pointwise gates + state update + scatter h into concat seq buffer.
// i=relu, f=relu, g=tanh, o=relu; c = f*c + i*g; h = o*tanh(c).
// fwd writes time j, bwd writes time T-1-j (implements sb[:, ::-1]).
// ---------------------------------------------------------------------------
template <int F>
__global__ void gate_step_kernel(const float* __restrict__ zbuf,
                                 float* __restrict__ hstate,
                                 float* __restrict__ cstate,
                                 float* __restrict__ seq, int j, int H, int W,
                                 int seqC) {
    const int HW = H * W;
    const int total = 2 * BB * HW * F;
    int i = blockIdx.x * blockDim.x + threadIdx.x;
    if (i >= total) return;
    const int f = i % F;
    int r = i / F;
    const int pos = r % HW;
    r /= HW;
    const int b = r % BB;
    const int dir = r / BB;

    const size_t zb = ((size_t)(dir * BB + b) * HW + pos) * (4 * F);
    const float zi = zbuf[zb + f];
    const float zf = zbuf[zb + F + f];
    const float zg = zbuf[zb + 2 * F + f];
    const float zo = zbuf[zb + 3 * F + f];

    const float ig = fmaxf(zi, 0.f);
    const float fg = fmaxf(zf, 0.f);
    const float gg = tanhf(zg);
    const float og = fmaxf(zo, 0.f);

    const size_t si = ((size_t)(dir * BB + b) * HW + pos) * F + f;
    const float cn = fg * cstate[si] + ig * gg;
    const float hn = og * tanhf(cn);
    cstate[si] = cn;
    hstate[si] = hn;

    const int t = dir ? (TT - 1 - j) : j;
    seq[(((size_t)(b * TT + t) * HW) + pos) * seqC + dir * F + f] = hn;
}

// ---------------------------------------------------------------------------
// BN (eps=1e-3) then 2x2 max pool (SAME, even dims -> exact).
// ---------------------------------------------------------------------------
__global__ void bnpool_kernel(const float* __restrict__ in,
                              float* __restrict__ out,
                              const float* __restrict__ gg,
                              const float* __restrict__ bb,
                              const float* __restrict__ mm,
                              const float* __restrict__ vv, int H, int W,
                              int C) {
    const int HO = H / 2, WO = W / 2;
    const size_t total = (size_t)BB * TT * HO * WO * C;
    size_t i = (size_t)blockIdx.x * blockDim.x + threadIdx.x;
    if (i >= total) return;
    const int c = i % C;
    size_t r = i / C;
    const int x = r % WO;
    r /= WO;
    const int y = r % HO;
    r /= HO;
    const int t = r % TT;
    const int b = r / TT;

    const float scale = gg[c] * rsqrtf(vv[c] + 1e-3f);
    const float shift = bb[c] - mm[c] * scale;

    const float* base = in + ((size_t)(b * TT + t)) * H * W * C;
    float mx = -3.402823e38f;
#pragma unroll
    for (int dy = 0; dy < 2; dy++)
#pragma unroll
        for (int dx = 0; dx < 2; dx++) {
            float v =
                base[((size_t)(2 * y + dy) * W + (2 * x + dx)) * C + c] * scale +
                shift;
            mx = fmaxf(mx, v);
        }
    out[i] = mx;
}

// ---------------------------------------------------------------------------
// Host side
// ---------------------------------------------------------------------------
static float* sym_addr(const void* symbol) {
    void* p = nullptr;
    cudaGetSymbolAddress(&p, symbol);
    return (float*)p;
}

extern "C" void kernel_launch(void* const* d_in, const int* in_sizes, int n_in,
                              void* d_out, int out_size) {
    const float* x = (const float*)d_in[0];
    const float* w1f_x = (const float*)d_in[1];
    const float* w1f_h = (const float*)d_in[2];
    const float* b1f = (const float*)d_in[3];
    const float* w1b_x = (const float*)d_in[4];
    const float* w1b_h = (const float*)d_in[5];
    const float* b1b = (const float*)d_in[6];
    const float* w2f_x = (const float*)d_in[7];
    const float* w2f_h = (const float*)d_in[8];
    const float* b2f = (const float*)d_in[9];
    const float* w2b_x = (const float*)d_in[10];
    const float* w2b_h = (const float*)d_in[11];
    const float* b2b = (const float*)d_in[12];
    const float* w3f_x = (const float*)d_in[13];
    const float* w3f_h = (const float*)d_in[14];
    const float* b3f = (const float*)d_in[15];
    const float* w3b_x = (const float*)d_in[16];
    const float* w3b_h = (const float*)d_in[17];
    const float* b3b = (const float*)d_in[18];
    const float* bn1_g = (const float*)d_in[19];
    const float* bn1_b = (const float*)d_in[20];
    const float* bn1_m = (const float*)d_in[21];
    const float* bn1_v = (const float*)d_in[22];
    const float* bn2_g = (const float*)d_in[23];
    const float* bn2_b = (const float*)d_in[24];
    const float* bn2_m = (const float*)d_in[25];
    const float* bn2_v = (const float*)d_in[26];

    float* seq1 = sym_addr(g_seq1);
    float* p1 = sym_addr(g_p1);
    float* seq2 = sym_addr(g_seq2);
    float* p2 = sym_addr(g_p2);
    float* zp = sym_addr(g_z);
    float* hp = sym_addr(g_h);
    float* cp = sym_addr(g_c);
    float* w1f = sym_addr(g_w1f);
    float* w1b = sym_addr(g_w1b);
    float* w2f = sym_addr(g_w2f);
    float* w2b = sym_addr(g_w2b);
    float* w3f = sym_addr(g_w3f);
    float* w3b = sym_addr(g_w3b);

    float* out = (float*)d_out;

    // ---- weight concat ----
    concat_w_kernel<<<(9 * 38 * 128 + 255) / 256, 256>>>(w1f_x, w1f_h, w1f, 6, 32);
    concat_w_kernel<<<(9 * 38 * 128 + 255) / 256, 256>>>(w1b_x, w1b_h, w1b, 6, 32);
    concat_w_kernel<<<(9 * 96 * 128 + 255) / 256, 256>>>(w2f_x, w2f_h, w2f, 64, 32);
    concat_w_kernel<<<(9 * 96 * 128 + 255) / 256, 256>>>(w2b_x, w2b_h, w2b, 64, 32);
    concat_w_kernel<<<(9 * 76 * 48 + 255) / 256, 256>>>(w3f_x, w3f_h, w3f, 64, 12);
    concat_w_kernel<<<(9 * 76 * 48 + 255) / 256, 256>>>(w3b_x, w3b_h, w3b, 64, 12);

    // ================= Layer 1: 48x56, Cin=6, F=32 =================
    {
        const size_t st = (size_t)2 * BB * 48 * 56 * 32;
        cudaMemsetAsync(hp, 0, st * sizeof(float));
        cudaMemsetAsync(cp, 0, st * sizeof(float));
        dim3 grid((48 / 4) * (56 / 14), BB, 2);
        const int gtot = 2 * BB * 48 * 56 * 32;
        for (int j = 0; j < TT; j++) {
            conv_step_kernel<6, 32, 48, 56>
                <<<grid, 128>>>(x, hp, w1f, w1b, b1f, b1b, zp, j);
            gate_step_kernel<32><<<(gtot + 255) / 256, 256>>>(zp, hp, cp, seq1,
                                                              j, 48, 56, 64);
        }
        const size_t ptot = (size_t)BB * TT * 24 * 28 * 64;
        bnpool_kernel<<<(unsigned)((ptot + 255) / 256), 256>>>(
            seq1, p1, bn1_g, bn1_b, bn1_m, bn1_v, 48, 56, 64);
    }

    // ================= Layer 2: 24x28, Cin=64, F=32 =================
    {
        const size_t st = (size_t)2 * BB * 24 * 28 * 32;
        cudaMemsetAsync(hp, 0, st * sizeof(float));
        cudaMemsetAsync(cp, 0, st * sizeof(float));
        dim3 grid((24 / 4) * (28 / 14), BB, 2);
        const int gtot = 2 * BB * 24 * 28 * 32;
        for (int j = 0; j < TT; j++) {
            conv_step_kernel<64, 32, 24, 28>
                <<<grid, 128>>>(p1, hp, w2f, w2b, b2f, b2b, zp, j);
            gate_step_kernel<32><<<(gtot + 255) / 256, 256>>>(zp, hp, cp, seq2,
                                                              j, 24, 28, 64);
        }
        const size_t ptot = (size_t)BB * TT * 12 * 14 * 64;
        bnpool_kernel<<<(unsigned)((ptot + 255) / 256), 256>>>(
            seq2, p2, bn2_g, bn2_b, bn2_m, bn2_v, 24, 28, 64);
    }

    // ================= Layer 3: 12x14, Cin=64, F=12 =================
    {
        const size_t st = (size_t)2 * BB * 12 * 14 * 12;
        cudaMemsetAsync(hp, 0, st * sizeof(float));
        cudaMemsetAsync(cp, 0, st * sizeof(float));
        dim3 grid((12 / 4) * (14 / 14), BB, 2);
        const int gtot = 2 * BB * 12 * 14 * 12;
        for (int j = 0; j < TT; j++) {
            conv_step_kernel<64, 12, 12, 14>
                <<<grid, 48>>>(p2, hp, w3f, w3b, b3f, b3b, zp, j);
            // seq goes straight into d_out (seqC = 24)
            gate_step_kernel<12><<<(gtot + 255) / 256, 256>>>(zp, hp, cp, out,
                                                              j, 12, 14, 24);
        }
    }

    // ---- final states: fh, fc, bh, bc ----
    const size_t SEQ3 = (size_t)BB * TT * 12 * 14 * 24;  // 774144
    const size_t ST3 = (size_t)BB * 12 * 14 * 12;        // 16128
    cudaMemcpyAsync(out + SEQ3, hp, ST3 * sizeof(float),
                    cudaMemcpyDeviceToDevice);
    cudaMemcpyAsync(out + SEQ3 + ST3, cp, ST3 * sizeof(float),
                    cudaMemcpyDeviceToDevice);
    cudaMemcpyAsync(out + SEQ3 + 2 * ST3, hp + ST3, ST3 * sizeof(float),
                    cudaMemcpyDeviceToDevice);
    cudaMemcpyAsync(out + SEQ3 + 3 * ST3, cp + ST3, ST3 * sizeof(float),
                    cudaMemcpyDeviceToDevice);
}

// round 3
// speedup vs baseline: 1.1447x; 1.1447x over previous
#include <cuda_runtime.h>
#include <cstdint>
#include <math.h>

// ---------------------------------------------------------------------------
// Bidirectional 3-layer ConvLSTM encoder, fused conv+gate steps, f32x2 FMA.
// B=8, T=24. L1: 48x56 Cin=6 F=32. L2: 24x28 Cin=64 F=32. L3: 12x14 Cin=64 F=12.
// ---------------------------------------------------------------------------

#define BB 8
#define TT 24

typedef unsigned long long ull;

// ---- scratch (__device__ globals) ----
__device__ __align__(16) float g_seq1[(size_t)BB * TT * 48 * 56 * 64];
__device__ __align__(16) float g_p1  [(size_t)BB * TT * 24 * 28 * 64];
__device__ __align__(16) float g_seq2[(size_t)BB * TT * 24 * 28 * 64];
__device__ __align__(16) float g_p2  [(size_t)BB * TT * 12 * 14 * 64];
__device__ __align__(16) float g_hA  [(size_t)2 * BB * 48 * 56 * 32];
__device__ __align__(16) float g_hB  [(size_t)2 * BB * 48 * 56 * 32];
__device__ __align__(16) float g_c   [(size_t)2 * BB * 48 * 56 * 32];
__device__ __align__(16) float g_w1f[9 * 38 * 128], g_w1b[9 * 38 * 128];
__device__ __align__(16) float g_w2f[9 * 96 * 128], g_w2b[9 * 96 * 128];
__device__ __align__(16) float g_w3f[9 * 76 * 48],  g_w3b[9 * 76 * 48];

// ---------------------------------------------------------------------------
// Packed f32x2 helpers (Blackwell 2x fp32 path; ptxas never emits these).
// ---------------------------------------------------------------------------
__device__ __forceinline__ ull dup2(float s) {
    ull d;
    asm("mov.b64 %0, {%1, %1};" : "=l"(d) : "f"(s));
    return d;
}
__device__ __forceinline__ void ffma2(ull& d, ull a, ull b) {
    asm("fma.rn.f32x2 %0, %1, %2, %0;" : "+l"(d) : "l"(a), "l"(b));
}

// ---------------------------------------------------------------------------
// Weight concat: wcat[k][ic][oc], ic in [0,CIN) from Wx, [CIN,CIN+F) from Wh.
// ---------------------------------------------------------------------------
__global__ void concat_w_kernel(const float* __restrict__ wx,
                                const float* __restrict__ wh,
                                float* __restrict__ wcat, int CIN, int F) {
    int OC = 4 * F, CH = CIN + F;
    int total = 9 * CH * OC;
    for (int i = blockIdx.x * blockDim.x + threadIdx.x; i < total;
         i += gridDim.x * blockDim.x) {
        int oc = i % OC;
        int r = i / OC;
        int ic = r % CH;
        int k = r / CH;
        wcat[i] = (ic < CIN) ? wx[((size_t)k * CIN + ic) * OC + oc]
                             : wh[((size_t)k * F + (ic - CIN)) * OC + oc];
    }
}

// ---------------------------------------------------------------------------
// Fused recurrent step: 3x3 conv over [x|h] producing all 4F gates (f32x2
// packed over oc pairs), then LSTM update + scatter h, all in one kernel.
// grid = (tiles, B, 2dir), block = 4F threads.
// h is double-buffered (hin read, hout written): no cross-block races.
// ---------------------------------------------------------------------------
template <int CIN, int F, int H, int W, int TH>
__global__ __launch_bounds__(4 * F) void conv_lstm_step(
    const float* __restrict__ xin,     // [B,T,H,W,CIN]
    const float* __restrict__ hin,     // [2,B,H,W,F]
    float* __restrict__ hout,          // [2,B,H,W,F]
    float* __restrict__ cstate,        // [2,B,H,W,F]
    const float* __restrict__ wf, const float* __restrict__ wb,
    const float* __restrict__ bf, const float* __restrict__ bb,
    float* __restrict__ seq, int seqC, int j) {
    constexpr int OC = 4 * F;
    constexpr int OCP = OC / 2;
    constexpr int CH = CIN + F;
    constexpr int THS = TH / 2;
    constexpr int TW = 14, TW2 = 16;
    constexpr int CSTRIDE = ((TH + 2) * TW2) | 1;
    constexpr int TILES_W = W / TW;
    constexpr int SMEM_IN = CH * CSTRIDE;
    constexpr int SMEM_Z = TH * TW * OC;
    constexpr int SMEM = (SMEM_IN > SMEM_Z) ? SMEM_IN : SMEM_Z;

    __shared__ __align__(16) float smem[SMEM];

    const int dir = blockIdx.z;
    const int b = blockIdx.y;
    const int tile = blockIdx.x;
    const int ty0 = (tile / TILES_W) * TH;
    const int tx0 = (tile % TILES_W) * TW;
    const int t = dir ? (TT - 1 - j) : j;

    const float* wc = dir ? wb : wf;
    const float* bi = dir ? bb : bf;
    const float* xb = xin + ((size_t)(b * TT + t)) * H * W * CIN;
    const float* hb = hin + ((size_t)(dir * BB + b)) * H * W * F;

    const int tid = threadIdx.x;

    // ---- halo load: global [y][x][c] -> smem [c][y][x] ----
    constexpr int TOTAL = (TH + 2) * TW2 * CH;
    for (int idx = tid; idx < TOTAL; idx += OC) {
        int c = idx % CH;
        int p = idx / CH;
        int yy = p / TW2, xx = p % TW2;
        int gy = ty0 + yy - 1, gx = tx0 + xx - 1;
        float v = 0.f;
        if (gy >= 0 && gy < H && gx >= 0 && gx < W) {
            v = (c < CIN) ? xb[((size_t)gy * W + gx) * CIN + c]
                          : hb[((size_t)gy * W + gx) * F + (c - CIN)];
        }
        smem[c * CSTRIDE + yy * TW2 + xx] = v;
    }
    __syncthreads();

    // ---- conv: each thread = oc pair (2*ocp, 2*ocp+1), THS rows x TW cols ----
    const int ocp = tid % OCP;
    const int sub = tid / OCP;

    ull acc[THS][TW];
    {
        const ull bv = *reinterpret_cast<const ull*>(bi + 2 * ocp);
#pragma unroll
        for (int y = 0; y < THS; y++)
#pragma unroll
            for (int p = 0; p < TW; p++) acc[y][p] = bv;
    }

    for (int c = 0; c < CH; c++) {
        const float* sc = smem + c * CSTRIDE + sub * THS * TW2;
        ull w[9];
#pragma unroll
        for (int k = 0; k < 9; k++)
            w[k] = *reinterpret_cast<const ull*>(wc + ((size_t)k * CH + c) * OC +
                                                 2 * ocp);
#pragma unroll
        for (int iy = 0; iy < THS + 2; iy++) {
            ull sd[TW2];
#pragma unroll
            for (int k = 0; k < TW2; k++) sd[k] = dup2(sc[iy * TW2 + k]);
#pragma unroll
            for (int dy = 0; dy < 3; dy++) {
                const int ry = iy - dy;
                if (ry >= 0 && ry < THS) {
#pragma unroll
                    for (int dx = 0; dx < 3; dx++) {
#pragma unroll
                        for (int p = 0; p < TW; p++)
                            ffma2(acc[ry][p], w[dy * 3 + dx], sd[p + dx]);
                    }
                }
            }
        }
    }

    // ---- exchange gate pre-activations via smem (reuse input buffer) ----
    __syncthreads();
#pragma unroll
    for (int y = 0; y < THS; y++)
#pragma unroll
        for (int p = 0; p < TW; p++)
            *reinterpret_cast<ull*>(smem + ((sub * THS + y) * TW + p) * OC +
                                    2 * ocp) = acc[y][p];
    __syncthreads();

    // ---- LSTM gate update + scatter ----
    const int f = tid % F;
    const int pidx = tid / F;  // 0..3
    float* hob = hout + ((size_t)(dir * BB + b)) * H * W * F;
    float* cb = cstate + ((size_t)(dir * BB + b)) * H * W * F;
    float* sb = seq + ((size_t)(b * TT + t)) * H * W * seqC + dir * F;

#pragma unroll
    for (int pos = pidx; pos < TH * TW; pos += 4) {
        const int y = pos / TW, x = pos % TW;
        const float zi = smem[pos * OC + f];
        const float zf = smem[pos * OC + F + f];
        const float zg = smem[pos * OC + 2 * F + f];
        const float zo = smem[pos * OC + 3 * F + f];

        const float ig = fmaxf(zi, 0.f);
        const float fg = fmaxf(zf, 0.f);
        const float gg = tanhf(zg);
        const float og = fmaxf(zo, 0.f);

        const size_t gi = (size_t)(ty0 + y) * W + (tx0 + x);
        const float cn = fg * cb[gi * F + f] + ig * gg;
        const float hn = og * tanhf(cn);
        cb[gi * F + f] = cn;
        hob[gi * F + f] = hn;
        sb[gi * seqC + f] = hn;
    }
}

// ---------------------------------------------------------------------------
// BN (eps=1e-3) then 2x2 max pool.
// ---------------------------------------------------------------------------
__global__ void bnpool_kernel(const float* __restrict__ in,
                              float* __restrict__ out,
                              const float* __restrict__ gg,
                              const float* __restrict__ bb,
                              const float* __restrict__ mm,
                              const float* __restrict__ vv, int H, int W,
                              int C) {
    const int HO = H / 2, WO = W / 2;
    const size_t total = (size_t)BB * TT * HO * WO * C;
    size_t i = (size_t)blockIdx.x * blockDim.x + threadIdx.x;
    if (i >= total) return;
    const int c = i % C;
    size_t r = i / C;
    const int x = r % WO;
    r /= WO;
    const int y = r % HO;
    r /= HO;
    const int t = r % TT;
    const int b = r / TT;

    const float scale = gg[c] * rsqrtf(vv[c] + 1e-3f);
    const float shift = bb[c] - mm[c] * scale;

    const float* base = in + ((size_t)(b * TT + t)) * H * W * C;
    float mx = -3.402823e38f;
#pragma unroll
    for (int dy = 0; dy < 2; dy++)
#pragma unroll
        for (int dx = 0; dx < 2; dx++) {
            float v =
                base[((size_t)(2 * y + dy) * W + (2 * x + dx)) * C + c] * scale +
                shift;
            mx = fmaxf(mx, v);
        }
    out[i] = mx;
}

// ---------------------------------------------------------------------------
// Host side
// ---------------------------------------------------------------------------
static float* sym_addr(const void* symbol) {
    void* p = nullptr;
    cudaGetSymbolAddress(&p, symbol);
    return (float*)p;
}

extern "C" void kernel_launch(void* const* d_in, const int* in_sizes, int n_in,
                              void* d_out, int out_size) {
    const float* x = (const float*)d_in[0];
    const float* w1f_x = (const float*)d_in[1];
    const float* w1f_h = (const float*)d_in[2];
    const float* b1f = (const float*)d_in[3];
    const float* w1b_x = (const float*)d_in[4];
    const float* w1b_h = (const float*)d_in[5];
    const float* b1b = (const float*)d_in[6];
    const float* w2f_x = (const float*)d_in[7];
    const float* w2f_h = (const float*)d_in[8];
    const float* b2f = (const float*)d_in[9];
    const float* w2b_x = (const float*)d_in[10];
    const float* w2b_h = (const float*)d_in[11];
    const float* b2b = (const float*)d_in[12];
    const float* w3f_x = (const float*)d_in[13];
    const float* w3f_h = (const float*)d_in[14];
    const float* b3f = (const float*)d_in[15];
    const float* w3b_x = (const float*)d_in[16];
    const float* w3b_h = (const float*)d_in[17];
    const float* b3b = (const float*)d_in[18];
    const float* bn1_g = (const float*)d_in[19];
    const float* bn1_b = (const float*)d_in[20];
    const float* bn1_m = (const float*)d_in[21];
    const float* bn1_v = (const float*)d_in[22];
    const float* bn2_g = (const float*)d_in[23];
    const float* bn2_b = (const float*)d_in[24];
    const float* bn2_m = (const float*)d_in[25];
    const float* bn2_v = (const float*)d_in[26];

    float* seq1 = sym_addr(g_seq1);
    float* p1 = sym_addr(g_p1);
    float* seq2 = sym_addr(g_seq2);
    float* p2 = sym_addr(g_p2);
    float* hA = sym_addr(g_hA);
    float* hB = sym_addr(g_hB);
    float* cp = sym_addr(g_c);
    float* w1f = sym_addr(g_w1f);
    float* w1b = sym_addr(g_w1b);
    float* w2f = sym_addr(g_w2f);
    float* w2b = sym_addr(g_w2b);
    float* w3f = sym_addr(g_w3f);
    float* w3b = sym_addr(g_w3b);

    float* out = (float*)d_out;
    float* hbuf[2] = {hA, hB};

    // ---- weight concat ----
    concat_w_kernel<<<(9 * 38 * 128 + 255) / 256, 256>>>(w1f_x, w1f_h, w1f, 6, 32);
    concat_w_kernel<<<(9 * 38 * 128 + 255) / 256, 256>>>(w1b_x, w1b_h, w1b, 6, 32);
    concat_w_kernel<<<(9 * 96 * 128 + 255) / 256, 256>>>(w2f_x, w2f_h, w2f, 64, 32);
    concat_w_kernel<<<(9 * 96 * 128 + 255) / 256, 256>>>(w2b_x, w2b_h, w2b, 64, 32);
    concat_w_kernel<<<(9 * 76 * 48 + 255) / 256, 256>>>(w3f_x, w3f_h, w3f, 64, 12);
    concat_w_kernel<<<(9 * 76 * 48 + 255) / 256, 256>>>(w3b_x, w3b_h, w3b, 64, 12);

    // ================= Layer 1: 48x56, Cin=6, F=32, TH=4 =================
    {
        const size_t st = (size_t)2 * BB * 48 * 56 * 32;
        cudaMemsetAsync(hbuf[0], 0, st * sizeof(float));
        cudaMemsetAsync(cp, 0, st * sizeof(float));
        dim3 grid((48 / 4) * (56 / 14), BB, 2);
        for (int j = 0; j < TT; j++) {
            conv_lstm_step<6, 32, 48, 56, 4><<<grid, 128>>>(
                x, hbuf[j & 1], hbuf[(j + 1) & 1], cp, w1f, w1b, b1f, b1b,
                seq1, 64, j);
        }
        const size_t ptot = (size_t)BB * TT * 24 * 28 * 64;
        bnpool_kernel<<<(unsigned)((ptot + 255) / 256), 256>>>(
            seq1, p1, bn1_g, bn1_b, bn1_m, bn1_v, 48, 56, 64);
    }

    // ================= Layer 2: 24x28, Cin=64, F=32, TH=2 =================
    {
        const size_t st = (size_t)2 * BB * 24 * 28 * 32;
        cudaMemsetAsync(hbuf[0], 0, st * sizeof(float));
        cudaMemsetAsync(cp, 0, st * sizeof(float));
        dim3 grid((24 / 2) * (28 / 14), BB, 2);
        for (int j = 0; j < TT; j++) {
            conv_lstm_step<64, 32, 24, 28, 2><<<grid, 128>>>(
                p1, hbuf[j & 1], hbuf[(j + 1) & 1], cp, w2f, w2b, b2f, b2b,
                seq2, 64, j);
        }
        const size_t ptot = (size_t)BB * TT * 12 * 14 * 64;
        bnpool_kernel<<<(unsigned)((ptot + 255) / 256), 256>>>(
            seq2, p2, bn2_g, bn2_b, bn2_m, bn2_v, 24, 28, 64);
    }

    // ================= Layer 3: 12x14, Cin=64, F=12, TH=4 =================
    {
        const size_t st = (size_t)2 * BB * 12 * 14 * 12;
        cudaMemsetAsync(hbuf[0], 0, st * sizeof(float));
        cudaMemsetAsync(cp, 0, st * sizeof(float));
        dim3 grid((12 / 4) * (14 / 14), BB, 2);
        for (int j = 0; j < TT; j++) {
            conv_lstm_step<64, 12, 12, 14, 4><<<grid, 48>>>(
                p2, hbuf[j & 1], hbuf[(j + 1) & 1], cp, w3f, w3b, b3f, b3b,
                out, 24, j);
        }
    }

    // ---- final states: fh, fc, bh, bc (h ended in hbuf[0] after 24 steps) ----
    const size_t SEQ3 = (size_t)BB * TT * 12 * 14 * 24;
    const size_t ST3 = (size_t)BB * 12 * 14 * 12;
    cudaMemcpyAsync(out + SEQ3, hbuf[0], ST3 * sizeof(float),
                    cudaMemcpyDeviceToDevice);
    cudaMemcpyAsync(out + SEQ3 + ST3, cp, ST3 * sizeof(float),
                    cudaMemcpyDeviceToDevice);
    cudaMemcpyAsync(out + SEQ3 + 2 * ST3, hbuf[0] + ST3, ST3 * sizeof(float),
                    cudaMemcpyDeviceToDevice);
    cudaMemcpyAsync(out + SEQ3 + 3 * ST3, cp + ST3, ST3 * sizeof(float),
                    cudaMemcpyDeviceToDevice);
}

// round 4
// speedup vs baseline: 1.3961x; 1.2196x over previous
#include <cuda_runtime.h>
#include <cstdint>
#include <math.h>

// ---------------------------------------------------------------------------
// Bidirectional 3-layer ConvLSTM encoder, fused conv+gate steps (scalar FFMA,
// float4 broadcast smem reads).
// B=8, T=24. L1: 48x56 Cin=6 F=32. L2: 24x28 Cin=64 F=32. L3: 12x14 Cin=64 F=12.
// ---------------------------------------------------------------------------

#define BB 8
#define TT 24

// ---- scratch (__device__ globals) ----
__device__ __align__(16) float g_seq1[(size_t)BB * TT * 48 * 56 * 64];
__device__ __align__(16) float g_p1  [(size_t)BB * TT * 24 * 28 * 64];
__device__ __align__(16) float g_seq2[(size_t)BB * TT * 24 * 28 * 64];
__device__ __align__(16) float g_p2  [(size_t)BB * TT * 12 * 14 * 64];
__device__ __align__(16) float g_hA  [(size_t)2 * BB * 48 * 56 * 32];
__device__ __align__(16) float g_hB  [(size_t)2 * BB * 48 * 56 * 32];
__device__ __align__(16) float g_c   [(size_t)2 * BB * 48 * 56 * 32];
__device__ __align__(16) float g_w1f[9 * 38 * 128], g_w1b[9 * 38 * 128];
__device__ __align__(16) float g_w2f[9 * 96 * 128], g_w2b[9 * 96 * 128];
__device__ __align__(16) float g_w3f[9 * 76 * 48],  g_w3b[9 * 76 * 48];

// ---------------------------------------------------------------------------
// Merged weight concat: one launch builds all 6 wcat tensors.
// wcat[k][ic][oc], ic in [0,CIN) from Wx, [CIN,CIN+F) from Wh.
// ---------------------------------------------------------------------------
struct ConcatArgs {
    const float* wx[6];
    const float* wh[6];
    float* dst[6];
    int cin[6];
    int F[6];
};

__global__ void concat_all_kernel(ConcatArgs a) {
    const int which = blockIdx.y;
    const int CIN = a.cin[which], F = a.F[which];
    const int OC = 4 * F, CH = CIN + F;
    const int total = 9 * CH * OC;
    const float* wx = a.wx[which];
    const float* wh = a.wh[which];
    float* dst = a.dst[which];
    for (int i = blockIdx.x * blockDim.x + threadIdx.x; i < total;
         i += gridDim.x * blockDim.x) {
        int oc = i % OC;
        int r = i / OC;
        int ic = r % CH;
        int k = r / CH;
        dst[i] = (ic < CIN) ? wx[((size_t)k * CIN + ic) * OC + oc]
                            : wh[((size_t)k * F + (ic - CIN)) * OC + oc];
    }
}

// ---------------------------------------------------------------------------
// Fused recurrent step. grid = (tiles, B, 2dir), block = SUBS * OC threads.
// Thread (sub, oc): accumulates THS = TH/SUBS rows x TW cols for channel oc.
// All lanes of a warp share `sub` (OC % 32 == 0) -> smem reads are broadcast;
// loaded as float4 (rows 16B-aligned, CSTRIDE % 4 == 0).
// h double-buffered (hin read, hout written): no cross-block races.
// ---------------------------------------------------------------------------
template <int CIN, int F, int H, int W, int TH, int SUBS>
__global__ __launch_bounds__(SUBS * 4 * F) void conv_lstm_step(
    const float* __restrict__ xin,     // [B,T,H,W,CIN]
    const float* __restrict__ hin,     // [2,B,H,W,F]
    float* __restrict__ hout,          // [2,B,H,W,F]
    float* __restrict__ cstate,        // [2,B,H,W,F]
    const float* __restrict__ wf, const float* __restrict__ wb,
    const float* __restrict__ bf, const float* __restrict__ bb,
    float* __restrict__ seq, int seqC, int j) {
    constexpr int OC = 4 * F;
    constexpr int NT = SUBS * OC;
    constexpr int CH = CIN + F;
    constexpr int THS = TH / SUBS;
    constexpr int TW = 14, TW2 = 16;
    constexpr int CSTRIDE = (TH + 2) * TW2 + 4;   // mult of 4, 4-float skew
    constexpr int TILES_W = W / TW;
    constexpr int SMEM_IN = CH * CSTRIDE;
    constexpr int SMEM_Z = TH * TW * OC;
    constexpr int SMEM = (SMEM_IN > SMEM_Z) ? SMEM_IN : SMEM_Z;

    __shared__ __align__(16) float smem[SMEM];

    const int dir = blockIdx.z;
    const int b = blockIdx.y;
    const int tile = blockIdx.x;
    const int ty0 = (tile / TILES_W) * TH;
    const int tx0 = (tile % TILES_W) * TW;
    const int t = dir ? (TT - 1 - j) : j;

    const float* wc = dir ? wb : wf;
    const float* bi = dir ? bb : bf;
    const float* xb = xin + ((size_t)(b * TT + t)) * H * W * CIN;
    const float* hb = hin + ((size_t)(dir * BB + b)) * H * W * F;

    const int tid = threadIdx.x;

    // ---- halo load: global [y][x][c] -> smem [c][y][x] (coalesced reads) ----
    constexpr int TOTAL = (TH + 2) * TW2 * CH;
    for (int idx = tid; idx < TOTAL; idx += NT) {
        int c = idx % CH;
        int p = idx / CH;
        int yy = p / TW2, xx = p % TW2;
        int gy = ty0 + yy - 1, gx = tx0 + xx - 1;
        float v = 0.f;
        if (gy >= 0 && gy < H && gx >= 0 && gx < W) {
            v = (c < CIN) ? xb[((size_t)gy * W + gx) * CIN + c]
                          : hb[((size_t)gy * W + gx) * F + (c - CIN)];
        }
        smem[c * CSTRIDE + yy * TW2 + xx] = v;
    }
    __syncthreads();

    // ---- conv: thread = (sub, oc); THS rows x TW cols ----
    const int oc = tid % OC;
    const int sub = tid / OC;

    float acc[THS][TW];
    {
        const float bv = bi[oc];
#pragma unroll
        for (int y = 0; y < THS; y++)
#pragma unroll
            for (int p = 0; p < TW; p++) acc[y][p] = bv;
    }

    for (int c = 0; c < CH; c++) {
        const float* sc = smem + c * CSTRIDE + sub * THS * TW2;
        float w[9];
#pragma unroll
        for (int k = 0; k < 9; k++) w[k] = wc[((size_t)k * CH + c) * OC + oc];
#pragma unroll
        for (int iy = 0; iy < THS + 2; iy++) {
            float seg[TW2];
#pragma unroll
            for (int q = 0; q < TW2 / 4; q++) {
                const float4 v =
                    *reinterpret_cast<const float4*>(sc + iy * TW2 + 4 * q);
                seg[4 * q] = v.x;
                seg[4 * q + 1] = v.y;
                seg[4 * q + 2] = v.z;
                seg[4 * q + 3] = v.w;
            }
#pragma unroll
            for (int dy = 0; dy < 3; dy++) {
                const int ry = iy - dy;
                if (ry >= 0 && ry < THS) {
#pragma unroll
                    for (int dx = 0; dx < 3; dx++) {
                        const float ww = w[dy * 3 + dx];
#pragma unroll
                        for (int p = 0; p < TW; p++)
                            acc[ry][p] = fmaf(ww, seg[p + dx], acc[ry][p]);
                    }
                }
            }
        }
    }

    // ---- exchange gate pre-activations via smem (reuse input buffer) ----
    __syncthreads();
#pragma unroll
    for (int y = 0; y < THS; y++)
#pragma unroll
        for (int p = 0; p < TW; p++)
            smem[((sub * THS + y) * TW + p) * OC + oc] = acc[y][p];
    __syncthreads();

    // ---- LSTM gate update + scatter ----
    const int f = tid % F;
    const int pidx = tid / F;                 // 0 .. 4*SUBS-1
    constexpr int PSTRIDE = 4 * SUBS;
    float* hob = hout + ((size_t)(dir * BB + b)) * H * W * F;
    float* cb = cstate + ((size_t)(dir * BB + b)) * H * W * F;
    float* sb = seq + ((size_t)(b * TT + t)) * H * W * seqC + dir * F;

    for (int pos = pidx; pos < TH * TW; pos += PSTRIDE) {
        const int y = pos / TW, x = pos % TW;
        const float zi = smem[pos * OC + f];
        const float zf = smem[pos * OC + F + f];
        const float zg = smem[pos * OC + 2 * F + f];
        const float zo = smem[pos * OC + 3 * F + f];

        const float ig = fmaxf(zi, 0.f);
        const float fg = fmaxf(zf, 0.f);
        const float gg = tanhf(zg);
        const float og = fmaxf(zo, 0.f);

        const size_t gi = (size_t)(ty0 + y) * W + (tx0 + x);
        const float cn = fg * cb[gi * F + f] + ig * gg;
        const float hn = og * tanhf(cn);
        cb[gi * F + f] = cn;
        hob[gi * F + f] = hn;
        sb[gi * seqC + f] = hn;
    }
}

// ---------------------------------------------------------------------------
// BN (eps=1e-3) then 2x2 max pool.
// ---------------------------------------------------------------------------
__global__ void bnpool_kernel(const float* __restrict__ in,
                              float* __restrict__ out,
                              const float* __restrict__ gg,
                              const float* __restrict__ bb,
                              const float* __restrict__ mm,
                              const float* __restrict__ vv, int H, int W,
                              int C) {
    const int HO = H / 2, WO = W / 2;
    const size_t total = (size_t)BB * TT * HO * WO * C;
    size_t i = (size_t)blockIdx.x * blockDim.x + threadIdx.x;
    if (i >= total) return;
    const int c = i % C;
    size_t r = i / C;
    const int x = r % WO;
    r /= WO;
    const int y = r % HO;
    r /= HO;
    const int t = r % TT;
    const int b = r / TT;

    const float scale = gg[c] * rsqrtf(vv[c] + 1e-3f);
    const float shift = bb[c] - mm[c] * scale;

    const float* base = in + ((size_t)(b * TT + t)) * H * W * C;
    float mx = -3.402823e38f;
#pragma unroll
    for (int dy = 0; dy < 2; dy++)
#pragma unroll
        for (int dx = 0; dx < 2; dx++) {
            float v =
                base[((size_t)(2 * y + dy) * W + (2 * x + dx)) * C + c] * scale +
                shift;
            mx = fmaxf(mx, v);
        }
    out[i] = mx;
}

// ---------------------------------------------------------------------------
// Host side
// ---------------------------------------------------------------------------
static float* sym_addr(const void* symbol) {
    void* p = nullptr;
    cudaGetSymbolAddress(&p, symbol);
    return (float*)p;
}

extern "C" void kernel_launch(void* const* d_in, const int* in_sizes, int n_in,
                              void* d_out, int out_size) {
    const float* x = (const float*)d_in[0];
    const float* w1f_x = (const float*)d_in[1];
    const float* w1f_h = (const float*)d_in[2];
    const float* b1f = (const float*)d_in[3];
    const float* w1b_x = (const float*)d_in[4];
    const float* w1b_h = (const float*)d_in[5];
    const float* b1b = (const float*)d_in[6];
    const float* w2f_x = (const float*)d_in[7];
    const float* w2f_h = (const float*)d_in[8];
    const float* b2f = (const float*)d_in[9];
    const float* w2b_x = (const float*)d_in[10];
    const float* w2b_h = (const float*)d_in[11];
    const float* b2b = (const float*)d_in[12];
    const float* w3f_x = (const float*)d_in[13];
    const float* w3f_h = (const float*)d_in[14];
    const float* b3f = (const float*)d_in[15];
    const float* w3b_x = (const float*)d_in[16];
    const float* w3b_h = (const float*)d_in[17];
    const float* b3b = (const float*)d_in[18];
    const float* bn1_g = (const float*)d_in[19];
    const float* bn1_b = (const float*)d_in[20];
    const float* bn1_m = (const float*)d_in[21];
    const float* bn1_v = (const float*)d_in[22];
    const float* bn2_g = (const float*)d_in[23];
    const float* bn2_b = (const float*)d_in[24];
    const float* bn2_m = (const float*)d_in[25];
    const float* bn2_v = (const float*)d_in[26];

    float* seq1 = sym_addr(g_seq1);
    float* p1 = sym_addr(g_p1);
    float* seq2 = sym_addr(g_seq2);
    float* p2 = sym_addr(g_p2);
    float* hA = sym_addr(g_hA);
    float* hB = sym_addr(g_hB);
    float* cp = sym_addr(g_c);
    float* w1f = sym_addr(g_w1f);
    float* w1b = sym_addr(g_w1b);
    float* w2f = sym_addr(g_w2f);
    float* w2b = sym_addr(g_w2b);
    float* w3f = sym_addr(g_w3f);
    float* w3b = sym_addr(g_w3b);

    float* out = (float*)d_out;
    float* hbuf[2] = {hA, hB};

    // ---- single merged weight concat ----
    {
        ConcatArgs a;
        a.wx[0] = w1f_x; a.wh[0] = w1f_h; a.dst[0] = w1f; a.cin[0] = 6;  a.F[0] = 32;
        a.wx[1] = w1b_x; a.wh[1] = w1b_h; a.dst[1] = w1b; a.cin[1] = 6;  a.F[1] = 32;
        a.wx[2] = w2f_x; a.wh[2] = w2f_h; a.dst[2] = w2f; a.cin[2] = 64; a.F[2] = 32;
        a.wx[3] = w2b_x; a.wh[3] = w2b_h; a.dst[3] = w2b; a.cin[3] = 64; a.F[3] = 32;
        a.wx[4] = w3f_x; a.wh[4] = w3f_h; a.dst[4] = w3f; a.cin[4] = 64; a.F[4] = 12;
        a.wx[5] = w3b_x; a.wh[5] = w3b_h; a.dst[5] = w3b; a.cin[5] = 64; a.F[5] = 12;
        dim3 grid(96, 6);
        concat_all_kernel<<<grid, 256>>>(a);
    }

    // ================= Layer 1: 48x56, Cin=6, F=32, TH=4, SUBS=2 ===========
    {
        const size_t st = (size_t)2 * BB * 48 * 56 * 32;
        cudaMemsetAsync(hbuf[0], 0, st * sizeof(float));
        cudaMemsetAsync(cp, 0, st * sizeof(float));
        dim3 grid((48 / 4) * (56 / 14), BB, 2);
        for (int j = 0; j < TT; j++) {
            conv_lstm_step<6, 32, 48, 56, 4, 2><<<grid, 256>>>(
                x, hbuf[j & 1], hbuf[(j + 1) & 1], cp, w1f, w1b, b1f, b1b,
                seq1, 64, j);
        }
        const size_t ptot = (size_t)BB * TT * 24 * 28 * 64;
        bnpool_kernel<<<(unsigned)((ptot + 255) / 256), 256>>>(
            seq1, p1, bn1_g, bn1_b, bn1_m, bn1_v, 48, 56, 64);
    }

    // ================= Layer 2: 24x28, Cin=64, F=32, TH=2, SUBS=2 ==========
    {
        const size_t st = (size_t)2 * BB * 24 * 28 * 32;
        cudaMemsetAsync(hbuf[0], 0, st * sizeof(float));
        cudaMemsetAsync(cp, 0, st * sizeof(float));
        dim3 grid((24 / 2) * (28 / 14), BB, 2);
        for (int j = 0; j < TT; j++) {
            conv_lstm_step<64, 32, 24, 28, 2, 2><<<grid, 256>>>(
                p1, hbuf[j & 1], hbuf[(j + 1) & 1], cp, w2f, w2b, b2f, b2b,
                seq2, 64, j);
        }
        const size_t ptot = (size_t)BB * TT * 12 * 14 * 64;
        bnpool_kernel<<<(unsigned)((ptot + 255) / 256), 256>>>(
            seq2, p2, bn2_g, bn2_b, bn2_m, bn2_v, 24, 28, 64);
    }

    // ================= Layer 3: 12x14, Cin=64, F=12, TH=4, SUBS=4 ==========
    {
        const size_t st = (size_t)2 * BB * 12 * 14 * 12;
        cudaMemsetAsync(hbuf[0], 0, st * sizeof(float));
        cudaMemsetAsync(cp, 0, st * sizeof(float));
        dim3 grid((12 / 4) * (14 / 14), BB, 2);
        for (int j = 0; j < TT; j++) {
            conv_lstm_step<64, 12, 12, 14, 4, 4><<<grid, 192>>>(
                p2, hbuf[j & 1], hbuf[(j + 1) & 1], cp, w3f, w3b, b3f, b3b,
                out, 24, j);
        }
    }

    // ---- final states: fh, fc, bh, bc (h ended in hbuf[0] after 24 steps) ----
    const size_t SEQ3 = (size_t)BB * TT * 12 * 14 * 24;
    const size_t ST3 = (size_t)BB * 12 * 14 * 12;
    cudaMemcpyAsync(out + SEQ3, hbuf[0], ST3 * sizeof(float),
                    cudaMemcpyDeviceToDevice);
    cudaMemcpyAsync(out + SEQ3 + ST3, cp, ST3 * sizeof(float),
                    cudaMemcpyDeviceToDevice);
    cudaMemcpyAsync(out + SEQ3 + 2 * ST3, hbuf[0] + ST3, ST3 * sizeof(float),
                    cudaMemcpyDeviceToDevice);
    cudaMemcpyAsync(out + SEQ3 + 3 * ST3, cp + ST3, ST3 * sizeof(float),
                    cudaMemcpyDeviceToDevice);
}

// round 5
// speedup vs baseline: 1.8305x; 1.3112x over previous
#include <cuda_runtime.h>
#include <cstdint>
#include <math.h>

// ---------------------------------------------------------------------------
// Bidirectional 3-layer ConvLSTM encoder.
// Split design: x-conv (no recurrence) precomputed for ALL timesteps in
// parallel into zbase; serial per-step kernels do h-conv + gates only.
// L3 runs as a single persistent kernel (whole spatial tile per block).
// B=8, T=24. L1: 48x56 Cin=6 F=32. L2: 24x28 Cin=64 F=32. L3: 12x14 Cin=64 F=12.
// ---------------------------------------------------------------------------

#define BB 8
#define TT 24

// ---- scratch (__device__ globals) ----
__device__ __align__(16) float g_seq1[(size_t)BB * TT * 48 * 56 * 64];
__device__ __align__(16) float g_p1  [(size_t)BB * TT * 24 * 28 * 64];
__device__ __align__(16) float g_seq2[(size_t)BB * TT * 24 * 28 * 64];
__device__ __align__(16) float g_p2  [(size_t)BB * TT * 12 * 14 * 64];
__device__ __align__(16) float g_zbase[(size_t)2 * BB * TT * 48 * 56 * 128]; // 528MB, reused per layer
__device__ __align__(16) float g_hA  [(size_t)2 * BB * 48 * 56 * 32];
__device__ __align__(16) float g_hB  [(size_t)2 * BB * 48 * 56 * 32];
__device__ __align__(16) float g_c   [(size_t)2 * BB * 48 * 56 * 32];

// ---------------------------------------------------------------------------
// Parallel x-conv over ALL timesteps:
// zbase[dir][b][t][y][x][oc] = bias[oc] + conv3x3(x[b,t], Wx[dir])
// grid = (tiles, B*T, 2dir), block = SUBS*4F.
// ---------------------------------------------------------------------------
template <int CIN, int F, int H, int W, int TH, int SUBS>
__global__ __launch_bounds__(SUBS * 4 * F) void xconv_all(
    const float* __restrict__ xin,   // [B,T,H,W,CIN]
    const float* __restrict__ wxf, const float* __restrict__ wxb, // [3,3,CIN,OC]
    const float* __restrict__ bf, const float* __restrict__ bb,
    float* __restrict__ zbase) {
    constexpr int OC = 4 * F;
    constexpr int NT = SUBS * OC;
    constexpr int THS = TH / SUBS;
    constexpr int TW = 14, TW2 = 16;
    constexpr int CSTRIDE = (TH + 2) * TW2 + 4;
    constexpr int TILES_W = W / TW;

    __shared__ __align__(16) float smem[CIN * CSTRIDE];

    const int dir = blockIdx.z;
    const int bt = blockIdx.y;           // b*TT + t
    const int tile = blockIdx.x;
    const int ty0 = (tile / TILES_W) * TH;
    const int tx0 = (tile % TILES_W) * TW;

    const float* wx = dir ? wxb : wxf;
    const float* bi = dir ? bb : bf;
    const float* xb = xin + (size_t)bt * H * W * CIN;
    const int b = bt / TT, t = bt % TT;

    const int tid = threadIdx.x;

    // halo load x: global [y][x][c] -> smem [c][y][x]
    constexpr int TOTAL = (TH + 2) * TW2 * CIN;
    for (int idx = tid; idx < TOTAL; idx += NT) {
        int c = idx % CIN;
        int p = idx / CIN;
        int yy = p / TW2, xx = p % TW2;
        int gy = ty0 + yy - 1, gx = tx0 + xx - 1;
        float v = 0.f;
        if (gy >= 0 && gy < H && gx >= 0 && gx < W)
            v = xb[((size_t)gy * W + gx) * CIN + c];
        smem[c * CSTRIDE + yy * TW2 + xx] = v;
    }
    __syncthreads();

    const int oc = tid % OC;
    const int sub = tid / OC;

    float acc[THS][TW];
    {
        const float bv = bi[oc];
#pragma unroll
        for (int y = 0; y < THS; y++)
#pragma unroll
            for (int p = 0; p < TW; p++) acc[y][p] = bv;
    }

#pragma unroll 2
    for (int c = 0; c < CIN; c++) {
        const float* sc = smem + c * CSTRIDE + sub * THS * TW2;
        float w[9];
#pragma unroll
        for (int k = 0; k < 9; k++) w[k] = wx[((size_t)k * CIN + c) * OC + oc];
#pragma unroll
        for (int iy = 0; iy < THS + 2; iy++) {
            float seg[TW2];
#pragma unroll
            for (int q = 0; q < TW2 / 4; q++) {
                const float4 v =
                    *reinterpret_cast<const float4*>(sc + iy * TW2 + 4 * q);
                seg[4 * q] = v.x; seg[4 * q + 1] = v.y;
                seg[4 * q + 2] = v.z; seg[4 * q + 3] = v.w;
            }
#pragma unroll
            for (int dy = 0; dy < 3; dy++) {
                const int ry = iy - dy;
                if (ry >= 0 && ry < THS) {
#pragma unroll
                    for (int dx = 0; dx < 3; dx++) {
                        const float ww = w[dy * 3 + dx];
#pragma unroll
                        for (int p = 0; p < TW; p++)
                            acc[ry][p] = fmaf(ww, seg[p + dx], acc[ry][p]);
                    }
                }
            }
        }
    }

    float* zb = zbase + (((size_t)(dir * BB + b) * TT + t) * H * W +
                         (size_t)ty0 * W + tx0) * OC;
#pragma unroll
    for (int y = 0; y < THS; y++)
#pragma unroll
        for (int p = 0; p < TW; p++)
            zb[((size_t)(sub * THS + y) * W + p) * OC + oc] = acc[y][p];
}

// ---------------------------------------------------------------------------
// Serial step: z = zbase + conv3x3(h, Wh); gates; state update; scatter h.
// grid = (tiles, B, 2dir), block = SUBS*4F.  h double-buffered.
// ---------------------------------------------------------------------------
template <int F, int H, int W, int TH, int SUBS>
__global__ __launch_bounds__(SUBS * 4 * F) void hconv_step(
    const float* __restrict__ zbase,  // [2,B,T,H,W,OC]
    const float* __restrict__ hin,    // [2,B,H,W,F]
    float* __restrict__ hout,
    float* __restrict__ cstate,
    const float* __restrict__ whf, const float* __restrict__ whb, // [3,3,F,OC]
    float* __restrict__ seq, int seqC, int j) {
    constexpr int OC = 4 * F;
    constexpr int NT = SUBS * OC;
    constexpr int THS = TH / SUBS;
    constexpr int TW = 14, TW2 = 16;
    constexpr int CSTRIDE = (TH + 2) * TW2 + 4;
    constexpr int TILES_W = W / TW;
    constexpr int SMEM_IN = F * CSTRIDE;
    constexpr int SMEM_Z = TH * TW * OC;
    constexpr int SMEM = (SMEM_IN > SMEM_Z) ? SMEM_IN : SMEM_Z;

    __shared__ __align__(16) float smem[SMEM];

    const int dir = blockIdx.z;
    const int b = blockIdx.y;
    const int tile = blockIdx.x;
    const int ty0 = (tile / TILES_W) * TH;
    const int tx0 = (tile % TILES_W) * TW;
    const int t = dir ? (TT - 1 - j) : j;

    const float* wh = dir ? whb : whf;
    const float* hb = hin + ((size_t)(dir * BB + b)) * H * W * F;

    const int tid = threadIdx.x;

    // halo load h
    constexpr int TOTAL = (TH + 2) * TW2 * F;
    for (int idx = tid; idx < TOTAL; idx += NT) {
        int c = idx % F;
        int p = idx / F;
        int yy = p / TW2, xx = p % TW2;
        int gy = ty0 + yy - 1, gx = tx0 + xx - 1;
        float v = 0.f;
        if (gy >= 0 && gy < H && gx >= 0 && gx < W)
            v = hb[((size_t)gy * W + gx) * F + c];
        smem[c * CSTRIDE + yy * TW2 + xx] = v;
    }
    __syncthreads();

    const int oc = tid % OC;
    const int sub = tid / OC;

    // acc init from zbase (x-conv + bias precomputed)
    const float* zb = zbase + (((size_t)(dir * BB + b) * TT + t) * H * W +
                               (size_t)ty0 * W + tx0) * OC;
    float acc[THS][TW];
#pragma unroll
    for (int y = 0; y < THS; y++)
#pragma unroll
        for (int p = 0; p < TW; p++)
            acc[y][p] = zb[((size_t)(sub * THS + y) * W + p) * OC + oc];

#pragma unroll 2
    for (int c = 0; c < F; c++) {
        const float* sc = smem + c * CSTRIDE + sub * THS * TW2;
        float w[9];
#pragma unroll
        for (int k = 0; k < 9; k++) w[k] = wh[((size_t)k * F + c) * OC + oc];
#pragma unroll
        for (int iy = 0; iy < THS + 2; iy++) {
            float seg[TW2];
#pragma unroll
            for (int q = 0; q < TW2 / 4; q++) {
                const float4 v =
                    *reinterpret_cast<const float4*>(sc + iy * TW2 + 4 * q);
                seg[4 * q] = v.x; seg[4 * q + 1] = v.y;
                seg[4 * q + 2] = v.z; seg[4 * q + 3] = v.w;
            }
#pragma unroll
            for (int dy = 0; dy < 3; dy++) {
                const int ry = iy - dy;
                if (ry >= 0 && ry < THS) {
#pragma unroll
                    for (int dx = 0; dx < 3; dx++) {
                        const float ww = w[dy * 3 + dx];
#pragma unroll
                        for (int p = 0; p < TW; p++)
                            acc[ry][p] = fmaf(ww, seg[p + dx], acc[ry][p]);
                    }
                }
            }
        }
    }

    // exchange gate pre-activations via smem
    __syncthreads();
#pragma unroll
    for (int y = 0; y < THS; y++)
#pragma unroll
        for (int p = 0; p < TW; p++)
            smem[((sub * THS + y) * TW + p) * OC + oc] = acc[y][p];
    __syncthreads();

    // LSTM gate update + scatter
    const int f = tid % F;
    const int pidx = tid / F;
    constexpr int PSTRIDE = 4 * SUBS;
    float* hob = hout + ((size_t)(dir * BB + b)) * H * W * F;
    float* cb = cstate + ((size_t)(dir * BB + b)) * H * W * F;
    float* sb = seq + ((size_t)(b * TT + t)) * H * W * seqC + dir * F;

    for (int pos = pidx; pos < TH * TW; pos += PSTRIDE) {
        const int y = pos / TW, x = pos % TW;
        const float zi = smem[pos * OC + f];
        const float zf = smem[pos * OC + F + f];
        const float zg = smem[pos * OC + 2 * F + f];
        const float zo = smem[pos * OC + 3 * F + f];

        const float ig = fmaxf(zi, 0.f);
        const float fg = fmaxf(zf, 0.f);
        const float gg = tanhf(zg);
        const float og = fmaxf(zo, 0.f);

        const size_t gi = (size_t)(ty0 + y) * W + (tx0 + x);
        const float cn = fg * cb[gi * F + f] + ig * gg;
        const float hn = og * tanhf(cn);
        cb[gi * F + f] = cn;
        hob[gi * F + f] = hn;
        sb[gi * seqC + f] = hn;
    }
}

// ---------------------------------------------------------------------------
// Layer 3 persistent kernel: one block per (dir, b) owns the full 12x14 tile;
// loops all 24 steps internally. h in smem, c in regs, states -> d_out.
// grid = 16, block = 288 (48 oc * 6 subs; also 12 f * 24 pos-groups).
// ---------------------------------------------------------------------------
__global__ __launch_bounds__(288) void lstm3_persistent(
    const float* __restrict__ zbase,  // [2,B,T,168,48]
    const float* __restrict__ whf, const float* __restrict__ whb, // [3,3,12,48]
    float* __restrict__ out) {
    constexpr int F = 12, OC = 48, H = 12, W = 14, HW = H * W;
    constexpr int TW2 = 16, CSTR = (H + 2) * TW2 + 4;  // 228

    __shared__ __align__(16) float sh[F * CSTR];   // h halo (borders stay 0)
    __shared__ __align__(16) float sz[HW * OC];    // gate exchange

    const int dirb = blockIdx.x;
    const int dir = dirb / BB;
    const int b = dirb % BB;
    const float* wh = dir ? whb : whf;
    const int tid = threadIdx.x;

    for (int i = tid; i < F * CSTR; i += 288) sh[i] = 0.f;

    const int f = tid % F;
    const int pidx = tid / F;   // 0..23
    float creg[7];
#pragma unroll
    for (int k = 0; k < 7; k++) creg[k] = 0.f;

    const int oc = tid % OC;
    const int sub = tid / OC;   // 0..5

    for (int j = 0; j < TT; j++) {
        const int t = dir ? (TT - 1 - j) : j;
        __syncthreads();  // h halo ready (init or prev gate phase)

        const float* zb = zbase + ((size_t)dirb * TT + t) * HW * OC;
        float acc[2][14];
#pragma unroll
        for (int y = 0; y < 2; y++)
#pragma unroll
            for (int p = 0; p < 14; p++)
                acc[y][p] = zb[((sub * 2 + y) * W + p) * OC + oc];

#pragma unroll
        for (int c = 0; c < F; c++) {
            const float* sc = sh + c * CSTR + sub * 2 * TW2;
            float w[9];
#pragma unroll
            for (int k = 0; k < 9; k++) w[k] = wh[((size_t)k * F + c) * OC + oc];
#pragma unroll
            for (int iy = 0; iy < 4; iy++) {
                float seg[16];
#pragma unroll
                for (int q = 0; q < 4; q++) {
                    const float4 v =
                        *reinterpret_cast<const float4*>(sc + iy * TW2 + 4 * q);
                    seg[4 * q] = v.x; seg[4 * q + 1] = v.y;
                    seg[4 * q + 2] = v.z; seg[4 * q + 3] = v.w;
                }
#pragma unroll
                for (int dy = 0; dy < 3; dy++) {
                    const int ry = iy - dy;
                    if (ry >= 0 && ry < 2) {
#pragma unroll
                        for (int dx = 0; dx < 3; dx++) {
                            const float ww = w[dy * 3 + dx];
#pragma unroll
                            for (int p = 0; p < 14; p++)
                                acc[ry][p] = fmaf(ww, seg[p + dx], acc[ry][p]);
                        }
                    }
                }
            }
        }

        __syncthreads();
#pragma unroll
        for (int y = 0; y < 2; y++)
#pragma unroll
            for (int p = 0; p < 14; p++)
                sz[((sub * 2 + y) * W + p) * OC + oc] = acc[y][p];
        __syncthreads();

        float* sq = out + ((size_t)(b * TT + t) * HW) * 24 + dir * F;
#pragma unroll
        for (int k = 0; k < 7; k++) {
            const int pos = pidx + 24 * k;
            const float zi = sz[pos * OC + f];
            const float zf = sz[pos * OC + F + f];
            const float zg = sz[pos * OC + 2 * F + f];
            const float zo = sz[pos * OC + 3 * F + f];
            const float ig = fmaxf(zi, 0.f);
            const float fg = fmaxf(zf, 0.f);
            const float gg = tanhf(zg);
            const float og = fmaxf(zo, 0.f);
            const float cn = fg * creg[k] + ig * gg;
            const float hn = og * tanhf(cn);
            creg[k] = cn;
            sq[pos * 24 + f] = hn;
            const int y = pos / W, x = pos % W;
            sh[f * CSTR + (y + 1) * TW2 + (x + 1)] = hn;
        }
    }

    // final states: fh, fc (dir=0) / bh, bc (dir=1)
    __syncthreads();
    const size_t SEQ3 = (size_t)BB * TT * HW * 24;
    const size_t ST3 = (size_t)BB * HW * F;
    float* oh = out + SEQ3 + (size_t)(2 * dir) * ST3;
    float* ocst = out + SEQ3 + (size_t)(2 * dir + 1) * ST3;
#pragma unroll
    for (int k = 0; k < 7; k++) {
        const int pos = pidx + 24 * k;
        const int y = pos / W, x = pos % W;
        oh[((size_t)b * HW + pos) * F + f] = sh[f * CSTR + (y + 1) * TW2 + (x + 1)];
        ocst[((size_t)b * HW + pos) * F + f] = creg[k];
    }
}

// ---------------------------------------------------------------------------
// BN (eps=1e-3) then 2x2 max pool.
// ---------------------------------------------------------------------------
__global__ void bnpool_kernel(const float* __restrict__ in,
                              float* __restrict__ out,
                              const float* __restrict__ gg,
                              const float* __restrict__ bb,
                              const float* __restrict__ mm,
                              const float* __restrict__ vv, int H, int W,
                              int C) {
    const int HO = H / 2, WO = W / 2;
    const size_t total = (size_t)BB * TT * HO * WO * C;
    size_t i = (size_t)blockIdx.x * blockDim.x + threadIdx.x;
    if (i >= total) return;
    const int c = i % C;
    size_t r = i / C;
    const int x = r % WO;
    r /= WO;
    const int y = r % HO;
    r /= HO;
    const int t = r % TT;
    const int b = r / TT;

    const float scale = gg[c] * rsqrtf(vv[c] + 1e-3f);
    const float shift = bb[c] - mm[c] * scale;

    const float* base = in + ((size_t)(b * TT + t)) * H * W * C;
    float mx = -3.402823e38f;
#pragma unroll
    for (int dy = 0; dy < 2; dy++)
#pragma unroll
        for (int dx = 0; dx < 2; dx++) {
            float v =
                base[((size_t)(2 * y + dy) * W + (2 * x + dx)) * C + c] * scale +
                shift;
            mx = fmaxf(mx, v);
        }
    out[i] = mx;
}

// ---------------------------------------------------------------------------
// Host side
// ---------------------------------------------------------------------------
static float* sym_addr(const void* symbol) {
    void* p = nullptr;
    cudaGetSymbolAddress(&p, symbol);
    return (float*)p;
}

extern "C" void kernel_launch(void* const* d_in, const int* in_sizes, int n_in,
                              void* d_out, int out_size) {
    const float* x = (const float*)d_in[0];
    const float* w1f_x = (const float*)d_in[1];
    const float* w1f_h = (const float*)d_in[2];
    const float* b1f = (const float*)d_in[3];
    const float* w1b_x = (const float*)d_in[4];
    const float* w1b_h = (const float*)d_in[5];
    const float* b1b = (const float*)d_in[6];
    const float* w2f_x = (const float*)d_in[7];
    const float* w2f_h = (const float*)d_in[8];
    const float* b2f = (const float*)d_in[9];
    const float* w2b_x = (const float*)d_in[10];
    const float* w2b_h = (const float*)d_in[11];
    const float* b2b = (const float*)d_in[12];
    const float* w3f_x = (const float*)d_in[13];
    const float* w3f_h = (const float*)d_in[14];
    const float* b3f = (const float*)d_in[15];
    const float* w3b_x = (const float*)d_in[16];
    const float* w3b_h = (const float*)d_in[17];
    const float* b3b = (const float*)d_in[18];
    const float* bn1_g = (const float*)d_in[19];
    const float* bn1_b = (const float*)d_in[20];
    const float* bn1_m = (const float*)d_in[21];
    const float* bn1_v = (const float*)d_in[22];
    const float* bn2_g = (const float*)d_in[23];
    const float* bn2_b = (const float*)d_in[24];
    const float* bn2_m = (const float*)d_in[25];
    const float* bn2_v = (const float*)d_in[26];

    float* seq1 = sym_addr(g_seq1);
    float* p1 = sym_addr(g_p1);
    float* seq2 = sym_addr(g_seq2);
    float* p2 = sym_addr(g_p2);
    float* zb = sym_addr(g_zbase);
    float* hA = sym_addr(g_hA);
    float* hB = sym_addr(g_hB);
    float* cp = sym_addr(g_c);

    float* out = (float*)d_out;
    float* hbuf[2] = {hA, hB};

    // ================= Layer 1: 48x56, Cin=6, F=32 =================
    {
        xconv_all<6, 32, 48, 56, 4, 2><<<dim3(48, BB * TT, 2), 256>>>(
            x, w1f_x, w1b_x, b1f, b1b, zb);
        const size_t st = (size_t)2 * BB * 48 * 56 * 32;
        cudaMemsetAsync(hbuf[0], 0, st * sizeof(float));
        cudaMemsetAsync(cp, 0, st * sizeof(float));
        for (int j = 0; j < TT; j++) {
            hconv_step<32, 48, 56, 4, 2><<<dim3(48, BB, 2), 256>>>(
                zb, hbuf[j & 1], hbuf[(j + 1) & 1], cp, w1f_h, w1b_h,
                seq1, 64, j);
        }
        const size_t ptot = (size_t)BB * TT * 24 * 28 * 64;
        bnpool_kernel<<<(unsigned)((ptot + 255) / 256), 256>>>(
            seq1, p1, bn1_g, bn1_b, bn1_m, bn1_v, 48, 56, 64);
    }

    // ================= Layer 2: 24x28, Cin=64, F=32 =================
    {
        xconv_all<64, 32, 24, 28, 4, 2><<<dim3(12, BB * TT, 2), 256>>>(
            p1, w2f_x, w2b_x, b2f, b2b, zb);
        const size_t st = (size_t)2 * BB * 24 * 28 * 32;
        cudaMemsetAsync(hbuf[0], 0, st * sizeof(float));
        cudaMemsetAsync(cp, 0, st * sizeof(float));
        for (int j = 0; j < TT; j++) {
            hconv_step<32, 24, 28, 2, 2><<<dim3(24, BB, 2), 256>>>(
                zb, hbuf[j & 1], hbuf[(j + 1) & 1], cp, w2f_h, w2b_h,
                seq2, 64, j);
        }
        const size_t ptot = (size_t)BB * TT * 12 * 14 * 64;
        bnpool_kernel<<<(unsigned)((ptot + 255) / 256), 256>>>(
            seq2, p2, bn2_g, bn2_b, bn2_m, bn2_v, 24, 28, 64);
    }

    // ================= Layer 3: 12x14, Cin=64, F=12 (persistent) ===========
    {
        xconv_all<64, 12, 12, 14, 4, 4><<<dim3(3, BB * TT, 2), 192>>>(
            p2, w3f_x, w3b_x, b3f, b3b, zb);
        lstm3_persistent<<<16, 288>>>(zb, w3f_h, w3b_h, out);
    }
}